// round 9
// baseline (speedup 1.0000x reference)
#include <cuda_runtime.h>
#include <cuda_bf16.h>
#include <math.h>
#include <cstdint>

#define Bb 16
#define Cc 512
#define Hh 32
#define Ww 32
#define Nn 16384
#define Dd 32
#define Pp 16384   // Bb*Hh*Ww

// ---------------------------------------------------------------------------
// Scratch (__device__ globals; no allocation allowed)
// ---------------------------------------------------------------------------
__device__ float g_z[Pp * Dd];        // normalized projected latents [p][d]
__device__ float g_e[Nn * Dd];        // normalized codebook fp32 [n][d] (rows 128B aligned)
__device__ uint4 g_eb[Nn * 12];       // codebook bf16 split: [n][96 bf16] = [hi|mid|hi]
__device__ float g_tmax[(size_t)Pp * 512];  // per-position per-32-code-entry max
__device__ int   g_idx[Pp];
__device__ int   g_hist[Nn];
__device__ float g_loss_part[512];

// ---------------------------------------------------------------------------
// PTX helpers (baseline PTX only: no 'a'-features)
// ---------------------------------------------------------------------------
__device__ __forceinline__ uint32_t smem_u32(const void* p) {
    uint32_t a;
    asm("{ .reg .u64 t; cvta.to.shared.u64 t, %1; cvt.u32.u64 %0, t; }" : "=r"(a) : "l"(p));
    return a;
}
__device__ __forceinline__ void ldsm4(uint32_t* r, uint32_t addr) {
    asm volatile("ldmatrix.sync.aligned.m8n8.x4.shared.b16 {%0,%1,%2,%3}, [%4];"
                 : "=r"(r[0]), "=r"(r[1]), "=r"(r[2]), "=r"(r[3]) : "r"(addr));
}
__device__ __forceinline__ void mma16816(float* d, const uint32_t* a, const uint32_t* b) {
    asm volatile("mma.sync.aligned.m16n8k16.row.col.f32.bf16.bf16.f32 "
                 "{%0,%1,%2,%3}, {%4,%5,%6,%7}, {%8,%9}, {%0,%1,%2,%3};"
                 : "+f"(d[0]), "+f"(d[1]), "+f"(d[2]), "+f"(d[3])
                 : "r"(a[0]), "r"(a[1]), "r"(a[2]), "r"(a[3]), "r"(b[0]), "r"(b[1]));
}
__device__ __forceinline__ void cpasync16(uint32_t dst, const void* src) {
    asm volatile("cp.async.cg.shared.global [%0], [%1], 16;" :: "r"(dst), "l"(src));
}
#define CP_COMMIT() asm volatile("cp.async.commit_group;" ::: "memory")
#define CP_WAIT0()  asm volatile("cp.async.wait_group 0;" ::: "memory")
#define CP_WAIT1()  asm volatile("cp.async.wait_group 1;" ::: "memory")

__device__ __forceinline__ bool better(float xv, int xi, float yv, int yi) {
    return xv > yv || (xv == yv && xi < yi);
}

// ---------------------------------------------------------------------------
// K_prep_e: normalize codebook rows; fp32 copy + bf16 split [hi|mid|hi].
// Also zeroes the 8 histogram slots owned by this block (grid = Nn/8).
// ---------------------------------------------------------------------------
__global__ void k_prep_e(const float* __restrict__ emb) {
    int warp = threadIdx.x >> 5, lane = threadIdx.x & 31;
    if (threadIdx.x < 8) g_hist[blockIdx.x * 8 + threadIdx.x] = 0;
    int n = blockIdx.x * 8 + warp;
    float v = emb[n * Dd + lane];
    float ss = v * v;
    #pragma unroll
    for (int o = 16; o; o >>= 1) ss += __shfl_xor_sync(0xffffffffu, ss, o);
    float rn = 1.0f / fmaxf(sqrtf(ss), 1e-6f);
    float zn = v * rn;
    g_e[n * Dd + lane] = zn;

    __nv_bfloat16 h = __float2bfloat16(zn);
    __nv_bfloat16 m = __float2bfloat16(zn - __bfloat162float(h));
    __nv_bfloat16* gb = (__nv_bfloat16*)g_eb + (size_t)n * 96 + lane;
    gb[0]  = h;    // k-block 0: e_hi
    gb[32] = m;    // k-block 1: e_mid
    gb[64] = h;    // k-block 2: e_hi
}

// ---------------------------------------------------------------------------
// K1: projection (1x1 conv C->D) + L2 normalize along D.
// ---------------------------------------------------------------------------
__global__ __launch_bounds__(256) void k_project(const float* __restrict__ enc,
                                                 const float* __restrict__ pw,
                                                 const float* __restrict__ pb) {
    __shared__ float enc_s[64][32];
    __shared__ float proj_s[32][64];
    __shared__ float z_s[32][33];
    __shared__ float rn_s[32];

    int bh  = blockIdx.x;
    int tid = threadIdx.x;
    int w   = tid & 31;
    int dg  = tid >> 5;

    const float* encbase = enc + (size_t)(bh >> 5) * Cc * Hh * Ww + (size_t)(bh & 31) * Ww;

    float acc[4] = {0.f, 0.f, 0.f, 0.f};

    for (int c0 = 0; c0 < Cc; c0 += 64) {
        #pragma unroll
        for (int k = 0; k < 2; k++) {
            int i = tid + 256 * k;            // 0..511
            int cl = i >> 3, v = i & 7;
            *(float4*)&enc_s[cl][v * 4] =
                *(const float4*)(encbase + (size_t)(c0 + cl) * (Hh * Ww) + v * 4);
        }
        #pragma unroll
        for (int k = 0; k < 2; k++) {
            int i = tid + 256 * k;
            int d = i >> 4, c4 = i & 15;
            *(float4*)&proj_s[d][c4 * 4] =
                *(const float4*)(pw + d * Cc + c0 + c4 * 4);
        }
        __syncthreads();
        #pragma unroll 16
        for (int cl = 0; cl < 64; cl++) {
            float ev = enc_s[cl][w];
            #pragma unroll
            for (int j = 0; j < 4; j++) acc[j] += proj_s[dg + 8 * j][cl] * ev;
        }
        __syncthreads();
    }
    #pragma unroll
    for (int j = 0; j < 4; j++) z_s[dg + 8 * j][w] = acc[j] + pb[dg + 8 * j];
    __syncthreads();

    if (tid < 32) {
        float ss = 0.f;
        #pragma unroll
        for (int d = 0; d < 32; d++) { float v = z_s[d][tid]; ss += v * v; }
        rn_s[tid] = 1.0f / fmaxf(sqrtf(ss), 1e-6f);
    }
    __syncthreads();

    for (int i = tid; i < 1024; i += 256) {
        int ww = i >> 5, d = i & 31;
        g_z[((size_t)bh * 32 + ww) * Dd + d] = z_s[d][ww] * rn_s[ww];
    }
}

// ---------------------------------------------------------------------------
// K2: HMMA sims (bf16 3-split, K=96); per-position per-32-code-entry MAX only.
// CTA: 256 threads (8 warps), 64 positions; 2 CTAs/SM. Code tile = 128.
// Warp tiling M32 x N32: mg = w&1 (32 positions), ns = w>>1 (32-code slice).
// The 32-code slice is processed as TWO sequential n16 halves with a running
// per-position max -> live accumulators = 16 regs (not 32), so with the
// 48-reg hoisted A-fragment bank we stay well under the 128-reg cap
// (round-8's 32-reg acc + 48-reg afr spilled and regressed).
// B triple-buffered via cp.async wait_group 1.
// ---------------------------------------------------------------------------
#define A_BYTES   13312                       // 64 * 208
#define B_BYTES   26624                       // 128 * 208
#define SIMS_SMEM (A_BYTES + 3 * B_BYTES)     // 93184

__global__ __launch_bounds__(256, 2) void k_sims() {
    extern __shared__ __align__(16) char sm[];
    __nv_bfloat16* As = (__nv_bfloat16*)sm;   // stride 104 bf16 = 208 B
    uint32_t sbase = smem_u32(sm);

    int tid  = threadIdx.x;
    int lane = tid & 31;
    int w    = tid >> 5;      // 0..7
    int mg   = w & 1;         // m-group: positions mg*32..mg*32+31
    int ns   = w >> 1;        // n-slice: codes ns*32..ns*32+31 of the tile
    int tg   = lane & 3;
    int gr   = lane >> 2;     // row-in-group 0..7
    int pbase = blockIdx.x * 64;

    // ---- build A tile: [hi | hi | mid] per row (64 rows) ----
    for (int i = tid; i < 64 * 32; i += 256) {
        int row = i >> 5, d = i & 31;
        float z = g_z[(size_t)(pbase + row) * Dd + d];
        __nv_bfloat16 h = __float2bfloat16(z);
        __nv_bfloat16 m = __float2bfloat16(z - __bfloat162float(h));
        As[row * 104 + d]      = h;
        As[row * 104 + 32 + d] = h;
        As[row * 104 + 64 + d] = m;
    }

    // ---- cp.async addressing: row = tid>>1, 6 contiguous 16B segs ----
    uint32_t cprow = (uint32_t)(tid >> 1);
    uint32_t cpseg = (uint32_t)((tid & 1) * 6) * 16;
    uint32_t srcBase = cprow * 192 + cpseg;
    uint32_t dstBase = cprow * 208 + cpseg;

    // ---- prefetch B tiles 0 and 1 ----
    const char* ebase = (const char*)g_eb;
    #pragma unroll
    for (int j = 0; j < 6; j++)
        cpasync16(sbase + A_BYTES + dstBase + j * 16, ebase + srcBase + j * 16);
    CP_COMMIT();
    #pragma unroll
    for (int j = 0; j < 6; j++)
        cpasync16(sbase + A_BYTES + B_BYTES + dstBase + j * 16,
                  ebase + 24576 + srcBase + j * 16);
    CP_COMMIT();
    __syncthreads();

    // ---- A fragments: 2 m16-tiles x 6 k-steps, hoisted (48 regs) ----
    uint32_t afr[2][6][4];
    int q = lane >> 3, r = lane & 7;
    #pragma unroll
    for (int mt = 0; mt < 2; mt++) {
        uint32_t abase = sbase + (uint32_t)((mg * 32 + mt * 16 + (q & 1) * 8 + r) * 208
                                            + (q >> 1) * 16);
        #pragma unroll
        for (int kk = 0; kk < 6; kk++) ldsm4(afr[mt][kk], abase + kk * 32);
    }
    uint32_t brow_off = (uint32_t)((ns * 32 + (q >> 1) * 8 + r) * 208 + (q & 1) * 16);

    for (int t = 0; t < 128; t++) {
        if (t < 126) CP_WAIT1(); else CP_WAIT0();
        __syncthreads();
        if (t + 2 < 128) {
            const char* src = ebase + (size_t)(t + 2) * 24576 + srcBase;
            uint32_t dst = sbase + A_BYTES + ((t + 2) % 3) * B_BYTES + dstBase;
            #pragma unroll
            for (int j = 0; j < 6; j++)
                cpasync16(dst + j * 16, src + j * 16);
            CP_COMMIT();
        }

        uint32_t bb = sbase + A_BYTES + (t % 3) * B_BYTES + brow_off;

        // running per-position maxima across the two n16 halves
        float mmax[2][2];
        mmax[0][0] = mmax[0][1] = mmax[1][0] = mmax[1][1] = -3e38f;

        #pragma unroll 1
        for (int g = 0; g < 2; g++) {          // n16 half; NOT unrolled (reg cap)
            uint32_t bbg = bb + (uint32_t)g * (16 * 208);
            float acc[2][2][4];
            #pragma unroll
            for (int mt = 0; mt < 2; mt++)
                #pragma unroll
                for (int nb = 0; nb < 2; nb++)
                    #pragma unroll
                    for (int i = 0; i < 4; i++) acc[mt][nb][i] = 0.f;

            #pragma unroll
            for (int kk = 0; kk < 6; kk++) {
                uint32_t br[4];
                ldsm4(br, bbg + kk * 32);
                mma16816(acc[0][0], afr[0][kk], br);
                mma16816(acc[0][1], afr[0][kk], br + 2);
                mma16816(acc[1][0], afr[1][kk], br);
                mma16816(acc[1][1], afr[1][kk], br + 2);
            }

            #pragma unroll
            for (int mt = 0; mt < 2; mt++) {
                #pragma unroll
                for (int h = 0; h < 2; h++) {
                    float v = fmaxf(fmaxf(acc[mt][0][2*h], acc[mt][0][2*h+1]),
                                    fmaxf(acc[mt][1][2*h], acc[mt][1][2*h+1]));
                    mmax[mt][h] = fmaxf(mmax[mt][h], v);
                }
            }
        }

        // ---- epilogue: reduce across the 4 tg lanes; store entry max ----
        #pragma unroll
        for (int mt = 0; mt < 2; mt++) {
            #pragma unroll
            for (int h = 0; h < 2; h++) {
                float m = mmax[mt][h];
                m = fmaxf(m, __shfl_xor_sync(0xffffffffu, m, 1));
                m = fmaxf(m, __shfl_xor_sync(0xffffffffu, m, 2));
                if (tg == 0) {
                    int pos = mg * 32 + mt * 16 + h * 8 + gr;
                    g_tmax[(size_t)(pbase + pos) * 512 + t * 4 + ns] = m;
                }
            }
        }
    }
}

// ---------------------------------------------------------------------------
// K_pass2: per position, scan 512 entry maxima -> top-2 entries;
// exact fp32 rescore of their 64 codes (cooperative row loads);
// write argmax + histogram. One warp per position; 8 positions per block.
// ---------------------------------------------------------------------------
__global__ __launch_bounds__(256) void k_pass2() {
    __shared__ float zs[8][32];
    int tid  = threadIdx.x;
    int wp   = tid >> 5;
    int lane = tid & 31;
    int p    = blockIdx.x * 8 + wp;

    zs[wp][lane] = g_z[(size_t)p * Dd + lane];
    __syncwarp();

    // ---- top-2 entries (approx values, tie -> smaller entry id) ----
    const float4* tm = (const float4*)(g_tmax + (size_t)p * 512 + lane * 16);
    float v1 = -3e38f, v2 = -3e38f;
    int   e1 = 0, e2 = 0;
    #pragma unroll
    for (int qq = 0; qq < 4; qq++) {
        float4 f = tm[qq];
        float vv[4] = {f.x, f.y, f.z, f.w};
        #pragma unroll
        for (int j = 0; j < 4; j++) {
            int ei = lane * 16 + qq * 4 + j;
            if (vv[j] > v2) {
                if (vv[j] > v1) { v2 = v1; e2 = e1; v1 = vv[j]; e1 = ei; }
                else            { v2 = vv[j]; e2 = ei; }
            }
        }
    }
    #pragma unroll
    for (int o = 16; o; o >>= 1) {
        float ov1 = __shfl_xor_sync(0xffffffffu, v1, o);
        int   oe1 = __shfl_xor_sync(0xffffffffu, e1, o);
        float ov2 = __shfl_xor_sync(0xffffffffu, v2, o);
        int   oe2 = __shfl_xor_sync(0xffffffffu, e2, o);
        if (better(ov1, oe1, v1, e1)) {
            if (better(v1, e1, ov2, oe2)) { v2 = v1; e2 = e1; }
            else                          { v2 = ov2; e2 = oe2; }
            v1 = ov1; e1 = oe1;
        } else if (better(ov1, oe1, v2, e2)) { v2 = ov1; e2 = oe1; }
    }

    // ---- exact rescore, cooperative: lane = (cg = lane>>2, qt = lane&3) ----
    int cg = lane >> 2, qt = lane & 3;
    float zq[8];
    #pragma unroll
    for (int j = 0; j < 8; j++) zq[j] = zs[wp][qt * 8 + j];

    float bv = -3e38f;
    int   bi = 0;
    #pragma unroll
    for (int it = 0; it < 8; it++) {
        int ee = (it < 4) ? e1 : e2;
        int c  = ee * 32 + (it & 3) * 8 + cg;
        const float4* er = (const float4*)(g_e + (size_t)c * Dd + qt * 8);
        float4 a = er[0], b = er[1];
        float s = a.x * zq[0] + a.y * zq[1] + a.z * zq[2] + a.w * zq[3]
                + b.x * zq[4] + b.y * zq[5] + b.z * zq[6] + b.w * zq[7];
        s += __shfl_xor_sync(0xffffffffu, s, 1);
        s += __shfl_xor_sync(0xffffffffu, s, 2);
        if (better(s, c, bv, bi)) { bv = s; bi = c; }
    }
    #pragma unroll
    for (int o = 16; o >= 4; o >>= 1) {
        float ov = __shfl_xor_sync(0xffffffffu, bv, o);
        int   oi = __shfl_xor_sync(0xffffffffu, bi, o);
        if (better(ov, oi, bv, bi)) { bv = ov; bi = oi; }
    }
    if (lane == 0) {
        g_idx[p] = bi;
        atomicAdd(&g_hist[bi], 1);
    }
}

// ---------------------------------------------------------------------------
// K3: gather latents, quantization-loss partial, expand D->C, write out.
// ---------------------------------------------------------------------------
__global__ __launch_bounds__(256) void k_output(const float* __restrict__ ew,
                                                const float* __restrict__ eb,
                                                float* __restrict__ out) {
    __shared__ float lat_s[32][33];
    __shared__ float exp_s[64][32];
    __shared__ float red[256];

    int bh  = blockIdx.x;
    int b   = bh >> 5, h = bh & 31;
    int tid = threadIdx.x;
    int pbase = bh * 32;

    float lsum = 0.f;
    for (int i = tid; i < 1024; i += 256) {
        int ww = i >> 5, d = i & 31;
        int ix = g_idx[pbase + ww];
        float lv = g_e[(size_t)ix * Dd + d];
        lat_s[ww][d] = lv;
        float dz = g_z[((size_t)pbase + ww) * Dd + d] - lv;
        lsum += dz * dz;
    }
    red[tid] = lsum;
    __syncthreads();
    for (int s = 128; s; s >>= 1) {
        if (tid < s) red[tid] += red[tid + s];
        __syncthreads();
    }
    if (tid == 0) g_loss_part[bh] = red[0];

    int w   = tid & 31;
    int cg8 = tid >> 5;

    for (int c0 = 0; c0 < Cc; c0 += 64) {
        __syncthreads();
        #pragma unroll
        for (int k = 0; k < 2; k++) {
            int i = tid + 256 * k;           // 0..511
            int cl = i >> 3, v = i & 7;
            *(float4*)&exp_s[cl][v * 4] =
                *(const float4*)(ew + (size_t)(c0 + cl) * Dd + v * 4);
        }
        __syncthreads();
        #pragma unroll
        for (int jj = 0; jj < 8; jj++) {
            int cl = cg8 + 8 * jj;
            int c  = c0 + cl;
            float s = eb[c];
            #pragma unroll
            for (int d = 0; d < 32; d++) s += exp_s[cl][d] * lat_s[w][d];
            out[(((size_t)b * Cc + c) * Hh + h) * Ww + w] = s;
        }
    }
}

// ---------------------------------------------------------------------------
// K4: final scalars — loss mean and perplexity.
// ---------------------------------------------------------------------------
__global__ void k_scalars(float* __restrict__ out, int osz) {
    __shared__ float red[256];
    int tid = threadIdx.x;

    float s = 0.f;
    for (int i = tid; i < 512; i += 256) s += g_loss_part[i];
    red[tid] = s;
    __syncthreads();
    for (int st = 128; st; st >>= 1) {
        if (tid < st) red[tid] += red[tid + st];
        __syncthreads();
    }
    if (tid == 0) out[osz - 2] = red[0] / (float)(Pp * Dd);
    __syncthreads();

    float e = 0.f;
    const float inv = 1.0f / (float)Pp;
    for (int i = tid; i < Nn; i += 256) {
        int c = g_hist[i];
        if (c > 0) {
            float u = (float)c * inv;
            e -= u * logf(u + 1e-6f);
        }
    }
    red[tid] = e;
    __syncthreads();
    for (int st = 128; st; st >>= 1) {
        if (tid < st) red[tid] += red[tid + st];
        __syncthreads();
    }
    if (tid == 0) out[osz - 1] = expf(red[0]);
}

// ---------------------------------------------------------------------------
extern "C" void kernel_launch(void* const* d_in, const int* in_sizes, int n_in,
                              void* d_out, int out_size) {
    const float* enc = (const float*)d_in[0];   // encodings [B,C,H,W]
    const float* emb = (const float*)d_in[1];   // emb_weight [N,D]
    const float* pw  = (const float*)d_in[2];   // proj_w [D,C]
    const float* pb  = (const float*)d_in[3];   // proj_b [D]
    const float* ew  = (const float*)d_in[4];   // exp_w [C,D]
    const float* eb  = (const float*)d_in[5];   // exp_b [C]
    float* out = (float*)d_out;

    cudaFuncSetAttribute(k_sims, cudaFuncAttributeMaxDynamicSharedMemorySize, SIMS_SMEM);

    k_prep_e<<<Nn / 8, 256>>>(emb);
    k_project<<<Bb * Hh, 256>>>(enc, pw, pb);
    k_sims<<<Pp / 64, 256, SIMS_SMEM>>>();
    k_pass2<<<Pp / 8, 256>>>();
    k_output<<<Bb * Hh, 256>>>(ew, eb, out);
    k_scalars<<<1, 256>>>(out, out_size);
}

// round 10
// speedup vs baseline: 1.3341x; 1.3341x over previous
#include <cuda_runtime.h>
#include <cuda_bf16.h>
#include <math.h>
#include <cstdint>

#define Bb 16
#define Cc 512
#define Hh 32
#define Ww 32
#define Nn 16384
#define Dd 32
#define Pp 16384   // Bb*Hh*Ww

// ---------------------------------------------------------------------------
// Scratch (__device__ globals; no allocation allowed)
// ---------------------------------------------------------------------------
__device__ float g_z[Pp * Dd];        // normalized projected latents [p][d]
__device__ float g_e[Nn * Dd];        // normalized codebook fp32 [n][d] (rows 128B aligned)
__device__ uint4 g_eb[Nn * 8];        // codebook bf16 split: [n][64 bf16] = [hi|mid]
__device__ float g_tmax[(size_t)Pp * 512];  // per-position per-32-code-entry max
__device__ int   g_idx[Pp];
__device__ int   g_hist[Nn];
__device__ float g_loss_part[512];

// ---------------------------------------------------------------------------
// PTX helpers (baseline PTX only: no 'a'-features)
// ---------------------------------------------------------------------------
__device__ __forceinline__ uint32_t smem_u32(const void* p) {
    uint32_t a;
    asm("{ .reg .u64 t; cvta.to.shared.u64 t, %1; cvt.u32.u64 %0, t; }" : "=r"(a) : "l"(p));
    return a;
}
__device__ __forceinline__ void ldsm4(uint32_t* r, uint32_t addr) {
    asm volatile("ldmatrix.sync.aligned.m8n8.x4.shared.b16 {%0,%1,%2,%3}, [%4];"
                 : "=r"(r[0]), "=r"(r[1]), "=r"(r[2]), "=r"(r[3]) : "r"(addr));
}
__device__ __forceinline__ void mma16816(float* d, const uint32_t* a, const uint32_t* b) {
    asm volatile("mma.sync.aligned.m16n8k16.row.col.f32.bf16.bf16.f32 "
                 "{%0,%1,%2,%3}, {%4,%5,%6,%7}, {%8,%9}, {%0,%1,%2,%3};"
                 : "+f"(d[0]), "+f"(d[1]), "+f"(d[2]), "+f"(d[3])
                 : "r"(a[0]), "r"(a[1]), "r"(a[2]), "r"(a[3]), "r"(b[0]), "r"(b[1]));
}
__device__ __forceinline__ void cpasync16(uint32_t dst, const void* src) {
    asm volatile("cp.async.cg.shared.global [%0], [%1], 16;" :: "r"(dst), "l"(src));
}
#define CP_COMMIT() asm volatile("cp.async.commit_group;" ::: "memory")
#define CP_WAIT0()  asm volatile("cp.async.wait_group 0;" ::: "memory")
#define CP_WAIT1()  asm volatile("cp.async.wait_group 1;" ::: "memory")

__device__ __forceinline__ bool better(float xv, int xi, float yv, int yi) {
    return xv > yv || (xv == yv && xi < yi);
}

// ---------------------------------------------------------------------------
// K_prep_e: normalize codebook rows; fp32 copy + bf16 split [hi|mid].
// Also zeroes the 8 histogram slots owned by this block (grid = Nn/8).
// ---------------------------------------------------------------------------
__global__ void k_prep_e(const float* __restrict__ emb) {
    int warp = threadIdx.x >> 5, lane = threadIdx.x & 31;
    if (threadIdx.x < 8) g_hist[blockIdx.x * 8 + threadIdx.x] = 0;
    int n = blockIdx.x * 8 + warp;
    float v = emb[n * Dd + lane];
    float ss = v * v;
    #pragma unroll
    for (int o = 16; o; o >>= 1) ss += __shfl_xor_sync(0xffffffffu, ss, o);
    float rn = 1.0f / fmaxf(sqrtf(ss), 1e-6f);
    float zn = v * rn;
    g_e[n * Dd + lane] = zn;

    __nv_bfloat16 h = __float2bfloat16(zn);
    __nv_bfloat16 m = __float2bfloat16(zn - __bfloat162float(h));
    __nv_bfloat16* gb = (__nv_bfloat16*)g_eb + (size_t)n * 64 + lane;
    gb[0]  = h;    // k-block 0: e_hi
    gb[32] = m;    // k-block 1: e_mid
}

// ---------------------------------------------------------------------------
// K1: projection (1x1 conv C->D) + L2 normalize along D.
// ---------------------------------------------------------------------------
__global__ __launch_bounds__(256) void k_project(const float* __restrict__ enc,
                                                 const float* __restrict__ pw,
                                                 const float* __restrict__ pb) {
    __shared__ float enc_s[64][32];
    __shared__ float proj_s[32][64];
    __shared__ float z_s[32][33];
    __shared__ float rn_s[32];

    int bh  = blockIdx.x;
    int tid = threadIdx.x;
    int w   = tid & 31;
    int dg  = tid >> 5;

    const float* encbase = enc + (size_t)(bh >> 5) * Cc * Hh * Ww + (size_t)(bh & 31) * Ww;

    float acc[4] = {0.f, 0.f, 0.f, 0.f};

    for (int c0 = 0; c0 < Cc; c0 += 64) {
        #pragma unroll
        for (int k = 0; k < 2; k++) {
            int i = tid + 256 * k;            // 0..511
            int cl = i >> 3, v = i & 7;
            *(float4*)&enc_s[cl][v * 4] =
                *(const float4*)(encbase + (size_t)(c0 + cl) * (Hh * Ww) + v * 4);
        }
        #pragma unroll
        for (int k = 0; k < 2; k++) {
            int i = tid + 256 * k;
            int d = i >> 4, c4 = i & 15;
            *(float4*)&proj_s[d][c4 * 4] =
                *(const float4*)(pw + d * Cc + c0 + c4 * 4);
        }
        __syncthreads();
        #pragma unroll 16
        for (int cl = 0; cl < 64; cl++) {
            float ev = enc_s[cl][w];
            #pragma unroll
            for (int j = 0; j < 4; j++) acc[j] += proj_s[dg + 8 * j][cl] * ev;
        }
        __syncthreads();
    }
    #pragma unroll
    for (int j = 0; j < 4; j++) z_s[dg + 8 * j][w] = acc[j] + pb[dg + 8 * j];
    __syncthreads();

    if (tid < 32) {
        float ss = 0.f;
        #pragma unroll
        for (int d = 0; d < 32; d++) { float v = z_s[d][tid]; ss += v * v; }
        rn_s[tid] = 1.0f / fmaxf(sqrtf(ss), 1e-6f);
    }
    __syncthreads();

    for (int i = tid; i < 1024; i += 256) {
        int ww = i >> 5, d = i & 31;
        g_z[((size_t)bh * 32 + ww) * Dd + d] = z_s[d][ww] * rn_s[ww];
    }
}

// ---------------------------------------------------------------------------
// K2: HMMA sims (bf16 3-split via B-fragment reuse, K_smem=64);
// per-position per-32-code-entry MAX only.
// CTA: 256 threads (8 warps), 64 positions; 2 CTAs/SM. Code tile = 128.
// Warp: rg = w&3 (16 positions), nh = w>>2 (64 codes) — the proven 314-us
// round-6 tiling. Change vs round-6: B stores only [hi|mid] (128 B/row,
// stride 144 = 9x16 -> conflict-free LDSM); the zm*eh term reuses the eh
// B-fragments in registers, cutting B-LDSM and cp.async bytes by 33%.
// Terms: zh*eh + zh*em + zm*eh (identical numerics to [hi|hi|mid]x[hi|mid|hi]).
// ---------------------------------------------------------------------------
#define A_BYTES   9216                        // 64 * 144
#define B_BYTES   18432                       // 128 * 144
#define SIMS_SMEM (A_BYTES + 3 * B_BYTES)     // 64512

__global__ __launch_bounds__(256, 2) void k_sims() {
    extern __shared__ __align__(16) char sm[];
    __nv_bfloat16* As = (__nv_bfloat16*)sm;   // stride 72 bf16 = 144 B
    uint32_t sbase = smem_u32(sm);

    int tid  = threadIdx.x;
    int lane = tid & 31;
    int w    = tid >> 5;      // 0..7
    int rg   = w & 3;         // row group (16 positions)
    int nh   = w >> 2;        // n-half (64 codes)
    int tg   = lane & 3;
    int gr   = lane >> 2;     // row-in-group 0..7
    int pbase = blockIdx.x * 64;

    // ---- build A tile: [hi | mid] per row (64 rows, 144 B stride) ----
    for (int i = tid; i < 64 * 32; i += 256) {
        int row = i >> 5, d = i & 31;
        float z = g_z[(size_t)(pbase + row) * Dd + d];
        __nv_bfloat16 h = __float2bfloat16(z);
        __nv_bfloat16 m = __float2bfloat16(z - __bfloat162float(h));
        As[row * 72 + d]      = h;
        As[row * 72 + 32 + d] = m;
    }

    // ---- cp.async addressing: row = tid>>1, 4 chunks of 16B per thread ----
    // B tile = 128 codes x 128 B = 1024 x 16B chunks; 2 threads per row.
    uint32_t cprow = (uint32_t)(tid >> 1);
    uint32_t cphalf = (uint32_t)((tid & 1) * 64);
    uint32_t srcBase = cprow * 128 + cphalf;
    uint32_t dstBase = cprow * 144 + cphalf;

    // ---- prefetch B tiles 0 and 1 ----
    const char* ebase = (const char*)g_eb;
    #pragma unroll
    for (int j = 0; j < 4; j++)
        cpasync16(sbase + A_BYTES + dstBase + j * 16, ebase + srcBase + j * 16);
    CP_COMMIT();
    #pragma unroll
    for (int j = 0; j < 4; j++)
        cpasync16(sbase + A_BYTES + B_BYTES + dstBase + j * 16,
                  ebase + 16384 + srcBase + j * 16);
    CP_COMMIT();
    __syncthreads();

    // ---- A fragments: 4 k-steps (zh: 0,1; zm: 2,3), hoisted (16 regs) ----
    uint32_t afr[4][4];
    int q = lane >> 3, r = lane & 7;
    {
        uint32_t abase = sbase + (uint32_t)((rg * 16 + (q & 1) * 8 + r) * 144
                                            + (q >> 1) * 16);
        #pragma unroll
        for (int kk = 0; kk < 4; kk++) ldsm4(afr[kk], abase + kk * 32);
    }
    uint32_t brow_off = (uint32_t)((nh * 64 + (q >> 1) * 8 + r) * 144 + (q & 1) * 16);

    for (int t = 0; t < 128; t++) {
        if (t < 126) CP_WAIT1(); else CP_WAIT0();
        __syncthreads();
        if (t + 2 < 128) {
            const char* src = ebase + (size_t)(t + 2) * 16384 + srcBase;
            uint32_t dst = sbase + A_BYTES + ((t + 2) % 3) * B_BYTES + dstBase;
            #pragma unroll
            for (int j = 0; j < 4; j++)
                cpasync16(dst + j * 16, src + j * 16);
            CP_COMMIT();
        }

        uint32_t bb = sbase + A_BYTES + (t % 3) * B_BYTES + brow_off;
        float acc[8][4];
        #pragma unroll
        for (int nb = 0; nb < 8; nb++)
            #pragma unroll
            for (int i = 0; i < 4; i++) acc[nb][i] = 0.f;

        #pragma unroll
        for (int j = 0; j < 4; j++) {          // four n16 groups
            uint32_t bbj = bb + (uint32_t)j * (16 * 144);
            uint32_t beh0[4], beh1[4], bem0[4], bem1[4];
            ldsm4(beh0, bbj);                  // eh, k-step 0
            ldsm4(beh1, bbj + 32);             // eh, k-step 1
            ldsm4(bem0, bbj + 64);             // em, k-step 0
            ldsm4(bem1, bbj + 96);             // em, k-step 1
            // zh*eh
            mma16816(acc[2*j],   afr[0], beh0); mma16816(acc[2*j+1], afr[0], beh0 + 2);
            mma16816(acc[2*j],   afr[1], beh1); mma16816(acc[2*j+1], afr[1], beh1 + 2);
            // zh*em
            mma16816(acc[2*j],   afr[0], bem0); mma16816(acc[2*j+1], afr[0], bem0 + 2);
            mma16816(acc[2*j],   afr[1], bem1); mma16816(acc[2*j+1], afr[1], bem1 + 2);
            // zm*eh (reuses eh fragments — no extra LDSM)
            mma16816(acc[2*j],   afr[2], beh0); mma16816(acc[2*j+1], afr[2], beh0 + 2);
            mma16816(acc[2*j],   afr[3], beh1); mma16816(acc[2*j+1], afr[3], beh1 + 2);
        }

        // ---- per-entry max (value only, FMNMX trees + shfl) ----
        // acc 0..3 = codes nh*64+0..31 (entry nh*2), acc 4..7 = +32..63.
        float mA0, mA1, mB0, mB1;
        {
            float a0 = fmaxf(fmaxf(acc[0][0], acc[0][1]), fmaxf(acc[1][0], acc[1][1]));
            float a1 = fmaxf(fmaxf(acc[2][0], acc[2][1]), fmaxf(acc[3][0], acc[3][1]));
            mA0 = fmaxf(a0, a1);
            float a2 = fmaxf(fmaxf(acc[4][0], acc[4][1]), fmaxf(acc[5][0], acc[5][1]));
            float a3 = fmaxf(fmaxf(acc[6][0], acc[6][1]), fmaxf(acc[7][0], acc[7][1]));
            mA1 = fmaxf(a2, a3);
            float b0 = fmaxf(fmaxf(acc[0][2], acc[0][3]), fmaxf(acc[1][2], acc[1][3]));
            float b1 = fmaxf(fmaxf(acc[2][2], acc[2][3]), fmaxf(acc[3][2], acc[3][3]));
            mB0 = fmaxf(b0, b1);
            float b2 = fmaxf(fmaxf(acc[4][2], acc[4][3]), fmaxf(acc[5][2], acc[5][3]));
            float b3 = fmaxf(fmaxf(acc[6][2], acc[6][3]), fmaxf(acc[7][2], acc[7][3]));
            mB1 = fmaxf(b2, b3);
        }
        mA0 = fmaxf(mA0, __shfl_xor_sync(0xffffffffu, mA0, 1));
        mA0 = fmaxf(mA0, __shfl_xor_sync(0xffffffffu, mA0, 2));
        mA1 = fmaxf(mA1, __shfl_xor_sync(0xffffffffu, mA1, 1));
        mA1 = fmaxf(mA1, __shfl_xor_sync(0xffffffffu, mA1, 2));
        mB0 = fmaxf(mB0, __shfl_xor_sync(0xffffffffu, mB0, 1));
        mB0 = fmaxf(mB0, __shfl_xor_sync(0xffffffffu, mB0, 2));
        mB1 = fmaxf(mB1, __shfl_xor_sync(0xffffffffu, mB1, 1));
        mB1 = fmaxf(mB1, __shfl_xor_sync(0xffffffffu, mB1, 2));

        if (tg == 0) {
            int posA = rg * 16 + gr;                        // posB = posA + 8
            size_t ba = (size_t)(pbase + posA) * 512 + t * 4 + nh * 2;
            *(float2*)&g_tmax[ba] = make_float2(mA0, mA1);
            size_t bbx = ba + (size_t)8 * 512;
            *(float2*)&g_tmax[bbx] = make_float2(mB0, mB1);
        }
    }
}

// ---------------------------------------------------------------------------
// K_pass2: per position, scan 512 entry maxima -> top-2 entries;
// exact fp32 rescore of their 64 codes (cooperative row loads);
// write argmax + histogram. One warp per position; 8 positions per block.
// ---------------------------------------------------------------------------
__global__ __launch_bounds__(256) void k_pass2() {
    __shared__ float zs[8][32];
    int tid  = threadIdx.x;
    int wp   = tid >> 5;
    int lane = tid & 31;
    int p    = blockIdx.x * 8 + wp;

    zs[wp][lane] = g_z[(size_t)p * Dd + lane];
    __syncwarp();

    // ---- top-2 entries (approx values, tie -> smaller entry id) ----
    const float4* tm = (const float4*)(g_tmax + (size_t)p * 512 + lane * 16);
    float v1 = -3e38f, v2 = -3e38f;
    int   e1 = 0, e2 = 0;
    #pragma unroll
    for (int qq = 0; qq < 4; qq++) {
        float4 f = tm[qq];
        float vv[4] = {f.x, f.y, f.z, f.w};
        #pragma unroll
        for (int j = 0; j < 4; j++) {
            int ei = lane * 16 + qq * 4 + j;
            if (vv[j] > v2) {
                if (vv[j] > v1) { v2 = v1; e2 = e1; v1 = vv[j]; e1 = ei; }
                else            { v2 = vv[j]; e2 = ei; }
            }
        }
    }
    #pragma unroll
    for (int o = 16; o; o >>= 1) {
        float ov1 = __shfl_xor_sync(0xffffffffu, v1, o);
        int   oe1 = __shfl_xor_sync(0xffffffffu, e1, o);
        float ov2 = __shfl_xor_sync(0xffffffffu, v2, o);
        int   oe2 = __shfl_xor_sync(0xffffffffu, e2, o);
        if (better(ov1, oe1, v1, e1)) {
            if (better(v1, e1, ov2, oe2)) { v2 = v1; e2 = e1; }
            else                          { v2 = ov2; e2 = oe2; }
            v1 = ov1; e1 = oe1;
        } else if (better(ov1, oe1, v2, e2)) { v2 = ov1; e2 = oe1; }
    }

    // ---- exact rescore, cooperative: lane = (cg = lane>>2, qt = lane&3) ----
    int cg = lane >> 2, qt = lane & 3;
    float zq[8];
    #pragma unroll
    for (int j = 0; j < 8; j++) zq[j] = zs[wp][qt * 8 + j];

    float bv = -3e38f;
    int   bi = 0;
    #pragma unroll
    for (int it = 0; it < 8; it++) {
        int ee = (it < 4) ? e1 : e2;
        int c  = ee * 32 + (it & 3) * 8 + cg;
        const float4* er = (const float4*)(g_e + (size_t)c * Dd + qt * 8);
        float4 a = er[0], b = er[1];
        float s = a.x * zq[0] + a.y * zq[1] + a.z * zq[2] + a.w * zq[3]
                + b.x * zq[4] + b.y * zq[5] + b.z * zq[6] + b.w * zq[7];
        s += __shfl_xor_sync(0xffffffffu, s, 1);
        s += __shfl_xor_sync(0xffffffffu, s, 2);
        if (better(s, c, bv, bi)) { bv = s; bi = c; }
    }
    #pragma unroll
    for (int o = 16; o >= 4; o >>= 1) {
        float ov = __shfl_xor_sync(0xffffffffu, bv, o);
        int   oi = __shfl_xor_sync(0xffffffffu, bi, o);
        if (better(ov, oi, bv, bi)) { bv = ov; bi = oi; }
    }
    if (lane == 0) {
        g_idx[p] = bi;
        atomicAdd(&g_hist[bi], 1);
    }
}

// ---------------------------------------------------------------------------
// K3: gather latents, quantization-loss partial, expand D->C, write out.
// ---------------------------------------------------------------------------
__global__ __launch_bounds__(256) void k_output(const float* __restrict__ ew,
                                                const float* __restrict__ eb,
                                                float* __restrict__ out) {
    __shared__ float lat_s[32][33];
    __shared__ float exp_s[64][32];
    __shared__ float red[256];

    int bh  = blockIdx.x;
    int b   = bh >> 5, h = bh & 31;
    int tid = threadIdx.x;
    int pbase = bh * 32;

    float lsum = 0.f;
    for (int i = tid; i < 1024; i += 256) {
        int ww = i >> 5, d = i & 31;
        int ix = g_idx[pbase + ww];
        float lv = g_e[(size_t)ix * Dd + d];
        lat_s[ww][d] = lv;
        float dz = g_z[((size_t)pbase + ww) * Dd + d] - lv;
        lsum += dz * dz;
    }
    red[tid] = lsum;
    __syncthreads();
    for (int s = 128; s; s >>= 1) {
        if (tid < s) red[tid] += red[tid + s];
        __syncthreads();
    }
    if (tid == 0) g_loss_part[bh] = red[0];

    int w   = tid & 31;
    int cg8 = tid >> 5;

    for (int c0 = 0; c0 < Cc; c0 += 64) {
        __syncthreads();
        #pragma unroll
        for (int k = 0; k < 2; k++) {
            int i = tid + 256 * k;           // 0..511
            int cl = i >> 3, v = i & 7;
            *(float4*)&exp_s[cl][v * 4] =
                *(const float4*)(ew + (size_t)(c0 + cl) * Dd + v * 4);
        }
        __syncthreads();
        #pragma unroll
        for (int jj = 0; jj < 8; jj++) {
            int cl = cg8 + 8 * jj;
            int c  = c0 + cl;
            float s = eb[c];
            #pragma unroll
            for (int d = 0; d < 32; d++) s += exp_s[cl][d] * lat_s[w][d];
            out[(((size_t)b * Cc + c) * Hh + h) * Ww + w] = s;
        }
    }
}

// ---------------------------------------------------------------------------
// K4: final scalars — loss mean and perplexity.
// ---------------------------------------------------------------------------
__global__ void k_scalars(float* __restrict__ out, int osz) {
    __shared__ float red[256];
    int tid = threadIdx.x;

    float s = 0.f;
    for (int i = tid; i < 512; i += 256) s += g_loss_part[i];
    red[tid] = s;
    __syncthreads();
    for (int st = 128; st; st >>= 1) {
        if (tid < st) red[tid] += red[tid + st];
        __syncthreads();
    }
    if (tid == 0) out[osz - 2] = red[0] / (float)(Pp * Dd);
    __syncthreads();

    float e = 0.f;
    const float inv = 1.0f / (float)Pp;
    for (int i = tid; i < Nn; i += 256) {
        int c = g_hist[i];
        if (c > 0) {
            float u = (float)c * inv;
            e -= u * logf(u + 1e-6f);
        }
    }
    red[tid] = e;
    __syncthreads();
    for (int st = 128; st; st >>= 1) {
        if (tid < st) red[tid] += red[tid + st];
        __syncthreads();
    }
    if (tid == 0) out[osz - 1] = expf(red[0]);
}

// ---------------------------------------------------------------------------
extern "C" void kernel_launch(void* const* d_in, const int* in_sizes, int n_in,
                              void* d_out, int out_size) {
    const float* enc = (const float*)d_in[0];   // encodings [B,C,H,W]
    const float* emb = (const float*)d_in[1];   // emb_weight [N,D]
    const float* pw  = (const float*)d_in[2];   // proj_w [D,C]
    const float* pb  = (const float*)d_in[3];   // proj_b [D]
    const float* ew  = (const float*)d_in[4];   // exp_w [C,D]
    const float* eb  = (const float*)d_in[5];   // exp_b [C]
    float* out = (float*)d_out;

    cudaFuncSetAttribute(k_sims, cudaFuncAttributeMaxDynamicSharedMemorySize, SIMS_SMEM);

    k_prep_e<<<Nn / 8, 256>>>(emb);
    k_project<<<Bb * Hh, 256>>>(enc, pw, pb);
    k_sims<<<Pp / 64, 256, SIMS_SMEM>>>();
    k_pass2<<<Pp / 8, 256>>>();
    k_output<<<Bb * Hh, 256>>>(ew, eb, out);
    k_scalars<<<1, 256>>>(out, out_size);
}